// round 11
// baseline (speedup 1.0000x reference)
#include <cuda_runtime.h>

// ---------------- sizes ----------------
constexpr int B_ = 256;
constexpr int R_ = 8;
constexpr int C2 = 128;

// ---------------- scratch (device globals; allocation-free rule) ----------------
__device__ float g_sw1[48 * 1 * 5];
__device__ float g_sw2[128 * 48 * 5];
__device__ float g_sw3[80 * 128 * 5];
__device__ float g_p1[(size_t)B_ * 48 * 32 * 32];    // 50 MB  raw pooled conv1 (BN in conv2 loader)
__device__ float g_q2[(size_t)B_ * 128 * 16 * 16];   // 33.5 MB raw pooled conv2 (BN in conv3 loader)
__device__ float g_m3[B_ * 80];                      // conv3 spatial max per (b, ch)
__device__ float g_psum[B_ * R_ * 16];
__device__ float g_psq[B_ * R_ * 16];
__device__ float g_scale[C2];
__device__ float g_shift[C2];

// pad tables: top and left pads per rotation row (from reference L)
__device__ const int c_LT[8][3] = {{2,1,0},{2,1,1},{2,1,0},{1,1,1},{0,1,2},{0,1,2},{0,1,2},{1,1,1}};
__device__ const int c_LL[8][3] = {{0,1,2},{1,1,1},{2,1,0},{2,1,0},{2,1,0},{1,1,1},{0,1,2},{0,1,2}};

// Sparse tap offsets per rotation class (runtime; hoists to 5 regs).
// cls1 slot 4 is a dummy (weight is always 0 there by construction).
__device__ __forceinline__ void taps(int cls, int oy[5], int ox[5]) {
#pragma unroll
    for (int s = 0; s < 5; s++) {
        int a = 2 - s;
        if (cls == 0)      { oy[s] = a;                     ox[s] = -a; }
        else if (cls == 1) { oy[s] = (s < 4) ? (1 - s) : 0; ox[s] = 0;  }
        else if (cls == 2) { oy[s] = a;                     ox[s] = a;  }
        else               { oy[s] = 0;                     ox[s] = a;  }
    }
}

// ---------------- build sparse effective kernels ----------------
__global__ void k_build(const float* __restrict__ w1, const float* __restrict__ w2,
                        const float* __restrict__ w3)
{
    int idx = blockIdx.x * blockDim.x + threadIdx.x;
    const float* w; float* out;
    int oc, ic, icfull, ocper, g;
    if (idx < 48)                     { w = w1; out = g_sw1; oc = idx; ic = 0; icfull = 1;   ocper = 6;  g = 0;  }
    else if (idx < 48 + 6144)         { int p = idx - 48;        w = w2; out = g_sw2; oc = p / 48;  ic = p % 48;  icfull = 48;  ocper = 16; g = 6;  }
    else if (idx < 48 + 6144 + 10240) { int p = idx - 48 - 6144; w = w3; out = g_sw3; oc = p / 128; ic = p % 128; icfull = 128; ocper = 10; g = 16; }
    else return;

    int i  = oc / ocper;
    int co = oc % ocper;
    int i2 = (i + 4) & 7;
    int cls = i & 3;
    int sic = ic;
    if (g) {                     // rotateChannel applied i times
        int rin = ic / g, gg = ic - rin * g;
        sic = ((rin - i) & 7) * g + gg;
    }
    float acc[5] = {0.f, 0.f, 0.f, 0.f, 0.f};
#pragma unroll
    for (int j = 0; j < 3; j++) {
#pragma unroll
        for (int k = 0; k < 3; k++) {
            int dy = c_LT[i][j] + c_LT[i2][k];
            int dx = c_LL[i][j] + c_LL[i2][k];
            int slot = (cls == 1) ? (dy - 1) : ((cls == 3) ? dx : dy);
            float v = w[(co * icfull + sic) * 9 + j * 3 + k];
#pragma unroll
            for (int s = 0; s < 5; s++) if (slot == s) acc[s] += v;
        }
    }
#pragma unroll
    for (int s = 0; s < 5; s++) out[(oc * icfull + ic) * 5 + s] = acc[s];
}

// ======= conv1 single pass: conv + exact stats + raw pooled max -> p1 =======
__global__ __launch_bounds__(256, 2) void k_conv1_statspool(const float* __restrict__ x)
{
    __shared__ float s_in[68 * 68];
    __shared__ float rs[6][8], rq[6][8];
    int b = blockIdx.x, r = blockIdx.y, cls = r & 3;
    int t = threadIdx.x;
    const float* xb = x + (size_t)b * 4096;
    for (int i = t; i < 68 * 68; i += 256) {
        int yy = i / 68, xx = i - yy * 68;
        int gy = yy - 2, gx = xx - 2;
        float v = 0.f;
        if ((unsigned)gy < 64u && (unsigned)gx < 64u) v = xb[gy * 64 + gx];
        s_in[i] = v;
    }
    float w[6][5];
#pragma unroll
    for (int oc = 0; oc < 6; oc++)
#pragma unroll
        for (int s = 0; s < 5; s++) w[oc][s] = g_sw1[(r * 6 + oc) * 5 + s];
    int oy[5], ox[5]; taps(cls, oy, ox);
    int boff[5];
#pragma unroll
    for (int s = 0; s < 5; s++) boff[s] = oy[s] * 68 + ox[s];
    __syncthreads();

    int pr = t >> 3, pc0 = (t & 7) << 2;   // pooled: 32 rows x 32 cols, 4 cols/thread
    float ssum[6] = {0,0,0,0,0,0}, ssq[6] = {0,0,0,0,0,0};
    float mx[6][4];
#pragma unroll
    for (int oc = 0; oc < 6; oc++)
#pragma unroll
        for (int i = 0; i < 4; i++) mx[oc][i] = -3.4e38f;

#pragma unroll
    for (int i = 0; i < 4; i++) {
#pragma unroll
        for (int dy = 0; dy < 2; dy++) {
#pragma unroll
            for (int dx = 0; dx < 2; dx++) {
                int cy = 2 * pr + dy, cx = 2 * (pc0 + i) + dx;
                int base = (cy + 2) * 68 + cx + 2;
                float in5[5];
#pragma unroll
                for (int s = 0; s < 5; s++) in5[s] = s_in[base + boff[s]];
#pragma unroll
                for (int oc = 0; oc < 6; oc++) {
                    float a = 0.f;
#pragma unroll
                    for (int s = 0; s < 5; s++) a = fmaf(w[oc][s], in5[s], a);
                    mx[oc][i] = fmaxf(mx[oc][i], a);
                    ssum[oc] += a;
                    ssq[oc]  = fmaf(a, a, ssq[oc]);
                }
            }
        }
    }
#pragma unroll
    for (int oc = 0; oc < 6; oc++) {
        float4 o = make_float4(mx[oc][0], mx[oc][1], mx[oc][2], mx[oc][3]);
        *(float4*)&g_p1[((size_t)(b * 48 + r * 6 + oc)) * 1024 + pr * 32 + pc0] = o;
    }
    int lane = t & 31, wid = t >> 5;
#pragma unroll
    for (int oc = 0; oc < 6; oc++) {
        float s = ssum[oc], q = ssq[oc];
#pragma unroll
        for (int off = 16; off; off >>= 1) {
            s += __shfl_down_sync(0xffffffffu, s, off);
            q += __shfl_down_sync(0xffffffffu, q, off);
        }
        if (lane == 0) { rs[oc][wid] = s; rq[oc][wid] = q; }
    }
    __syncthreads();
    if (t < 6) {
        float S = 0.f, Q = 0.f;
#pragma unroll
        for (int wdx = 0; wdx < 8; wdx++) { S += rs[t][wdx]; Q += rq[t][wdx]; }
        int p = (b * 8 + r) * 6 + t;
        g_psum[p] = S; g_psq[p] = Q;
    }
}

// ---------------- parallel BN stats finalize ----------------
__global__ void k_stats_final(const float* __restrict__ gamma, const float* __restrict__ beta,
                              int Cc, float invN)
{
    int c = blockIdx.x;
    float S = 0.f, Q = 0.f;
    for (int i = threadIdx.x; i < 2048; i += 256) {
        S += g_psum[i * Cc + c];
        Q += g_psq[i * Cc + c];
    }
    __shared__ float ss[256], sq[256];
    int t = threadIdx.x;
    ss[t] = S; sq[t] = Q; __syncthreads();
    for (int st = 128; st > 0; st >>= 1) {
        if (t < st) { ss[t] += ss[t + st]; sq[t] += sq[t + st]; }
        __syncthreads();
    }
    if (t == 0) {
        float mean = ss[0] * invN;
        float var  = sq[0] * invN - mean * mean;
        float sc = gamma[c] / sqrtf(var + 1e-5f);
        float sh = beta[c] - mean * sc;
        for (int rr = 0; rr < R_; rr++) { g_scale[rr * Cc + c] = sc; g_shift[rr * Cc + c] = sh; }
    }
}

// ==== conv2: BN+ReLU fused in loader; 512 thr, 2px x 16oc, scalar FFMA ====
__global__ __launch_bounds__(512, 2) void k_conv2()
{
    __shared__ float s_in[6][1296];                   // 31104 B (6-ic chunk, 36x36 halo)
    __shared__ __align__(16) float s_w[6][16][8];     // 3072 B
    __shared__ float rs[16][16], rq[16][16];          // 2048 B
    int b = blockIdx.x, r = blockIdx.y, cls = r & 3;
    int t = threadIdx.x;
    int oy[5], ox[5]; taps(cls, oy, ox);
    int boff[5];
#pragma unroll
    for (int s = 0; s < 5; s++) boff[s] = oy[s] * 36 + ox[s];
    int row = t >> 4;           // 0..31 (warp w covers rows 2w, 2w+1)
    int x0  = (t & 15) << 1;    // 0..30
    int base = (row + 2) * 36 + x0 + 2;
    float acc[16][2];
#pragma unroll
    for (int o = 0; o < 16; o++) { acc[o][0] = 0.f; acc[o][1] = 0.f; }
    const float* pin = g_p1 + (size_t)b * 48 * 1024;
    const float* pw  = g_sw2 + (size_t)r * 16 * 48 * 5;
    for (int icc = 0; icc < 48; icc += 6) {
        for (int i = t; i < 6 * 1296; i += 512) {
            int ic = i / 1296; int rem = i - ic * 1296;
            int yy = rem / 36, xx = rem - yy * 36;
            int gy = yy - 2, gx = xx - 2;
            float v = 0.f;
            if ((unsigned)gy < 32u && (unsigned)gx < 32u) {
                float raw = pin[(icc + ic) * 1024 + gy * 32 + gx];
                v = fmaxf(0.f, fmaf(g_scale[icc + ic], raw, g_shift[icc + ic]));
            }
            s_in[ic][rem] = v;
        }
        if (t < 480) {          // 6 ic x 16 oc x 5 s
            int ic = t / 80; int rem = t - ic * 80; int oc = rem / 5; int s = rem - oc * 5;
            s_w[ic][oc][s] = pw[(oc * 48 + icc + ic) * 5 + s];
        }
        __syncthreads();
#pragma unroll 1
        for (int ic = 0; ic < 6; ic++) {
            float in5[5][2];
#pragma unroll
            for (int s = 0; s < 5; s++) {
                int off = base + boff[s];
                in5[s][0] = s_in[ic][off];
                in5[s][1] = s_in[ic][off + 1];
            }
#pragma unroll
            for (int oc = 0; oc < 16; oc++) {
                float4 w03 = *(const float4*)&s_w[ic][oc][0];
                float  w4  = s_w[ic][oc][4];
                float a0 = acc[oc][0], a1 = acc[oc][1];
                a0 = fmaf(w03.x, in5[0][0], a0);  a1 = fmaf(w03.x, in5[0][1], a1);
                a0 = fmaf(w03.y, in5[1][0], a0);  a1 = fmaf(w03.y, in5[1][1], a1);
                a0 = fmaf(w03.z, in5[2][0], a0);  a1 = fmaf(w03.z, in5[2][1], a1);
                a0 = fmaf(w03.w, in5[3][0], a0);  a1 = fmaf(w03.w, in5[3][1], a1);
                a0 = fmaf(w4,   in5[4][0], a0);  a1 = fmaf(w4,   in5[4][1], a1);
                acc[oc][0] = a0; acc[oc][1] = a1;
            }
        }
        __syncthreads();
    }
    // epilogue: fused exact stats + pooled raw 2x2 max (warp = rows 2w,2w+1)
    int lane = t & 31, wid = t >> 5;
    size_t qbase = (((size_t)b * 128) + r * 16) * 256 + wid * 16;
#pragma unroll
    for (int oc = 0; oc < 16; oc++) {
        float s = acc[oc][0] + acc[oc][1];
        float q = acc[oc][0] * acc[oc][0] + acc[oc][1] * acc[oc][1];
#pragma unroll
        for (int off = 16; off; off >>= 1) {
            s += __shfl_down_sync(0xffffffffu, s, off);
            q += __shfl_down_sync(0xffffffffu, q, off);
        }
        if (lane == 0) { rs[oc][wid] = s; rq[oc][wid] = q; }
        float m = fmaxf(acc[oc][0], acc[oc][1]);             // horizontal pair
        float o = fmaxf(m, __shfl_xor_sync(0xffffffffu, m, 16));  // row pair
        if (lane < 16) g_q2[qbase + (size_t)oc * 256 + lane] = o;
    }
    __syncthreads();
    if (t < 16) {
        float S = 0.f, Q = 0.f;
#pragma unroll
        for (int wdx = 0; wdx < 16; wdx++) { S += rs[t][wdx]; Q += rq[t][wdx]; }
        int p = (b * 8 + r) * 16 + t;
        g_psum[p] = S; g_psq[p] = Q;
    }
}

// ==== conv3: BN+ReLU fused in loader; 2 batches/block, scalar FFMA -> max ====
__global__ __launch_bounds__(256, 4) void k_conv3()
{
    __shared__ float s_in[4][2][400];                 // 12800 B [ic][batch][20x20]
    __shared__ __align__(16) float s_w[4][10][8];     // 1280 B
    __shared__ float rmax[20][8];                     // 640 B
    int bb = blockIdx.x, r = blockIdx.y, cls = r & 3; // bb: 0..127 (batch pairs)
    int t = threadIdx.x;
    int oy[5], ox[5]; taps(cls, oy, ox);
    int boff[5];
#pragma unroll
    for (int s = 0; s < 5; s++) boff[s] = oy[s] * 20 + ox[s];
    int y = t >> 4, x = t & 15;
    int base = (y + 2) * 20 + x + 2;
    float acc[2][10];
#pragma unroll
    for (int b_ = 0; b_ < 2; b_++)
#pragma unroll
        for (int oc = 0; oc < 10; oc++) acc[b_][oc] = 0.f;
    const float* pw = g_sw3 + (size_t)r * 10 * 128 * 5;
    for (int icc = 0; icc < 128; icc += 4) {
        for (int i = t; i < 3200; i += 256) {
            int ic = i / 800; int rem = i - ic * 800;
            int b_ = rem / 400; int rem2 = rem - b_ * 400;
            int yy = rem2 / 20, xx = rem2 - yy * 20;
            int gy = yy - 2, gx = xx - 2;
            float v = 0.f;
            if ((unsigned)gy < 16u && (unsigned)gx < 16u) {
                float raw = g_q2[(((size_t)(bb * 2 + b_) * 128) + icc + ic) * 256 + gy * 16 + gx];
                v = fmaxf(0.f, fmaf(g_scale[icc + ic], raw, g_shift[icc + ic]));
            }
            s_in[ic][b_][rem2] = v;
        }
        if (t < 200) {          // 4 ic x 10 oc x 5 s
            int ic = t / 50; int rem = t - ic * 50; int oc = rem / 5; int s = rem - oc * 5;
            s_w[ic][oc][s] = pw[(oc * 128 + icc + ic) * 5 + s];
        }
        __syncthreads();
#pragma unroll 1
        for (int ic = 0; ic < 4; ic++) {
            float in5[5][2];
#pragma unroll
            for (int s = 0; s < 5; s++) {
                in5[s][0] = s_in[ic][0][base + boff[s]];
                in5[s][1] = s_in[ic][1][base + boff[s]];
            }
#pragma unroll
            for (int oc = 0; oc < 10; oc++) {
                float4 w03 = *(const float4*)&s_w[ic][oc][0];
                float  w4  = s_w[ic][oc][4];
#pragma unroll
                for (int b_ = 0; b_ < 2; b_++) {
                    float a = acc[b_][oc];
                    a = fmaf(w03.x, in5[0][b_], a);
                    a = fmaf(w03.y, in5[1][b_], a);
                    a = fmaf(w03.z, in5[2][b_], a);
                    a = fmaf(w03.w, in5[3][b_], a);
                    a = fmaf(w4,   in5[4][b_], a);
                    acc[b_][oc] = a;
                }
            }
        }
        __syncthreads();
    }
    // in-block spatial max per (b_, oc)
    int lane = t & 31, wid = t >> 5;
#pragma unroll
    for (int b_ = 0; b_ < 2; b_++)
#pragma unroll
        for (int oc = 0; oc < 10; oc++) {
            float m = acc[b_][oc];
#pragma unroll
            for (int off = 16; off; off >>= 1)
                m = fmaxf(m, __shfl_down_sync(0xffffffffu, m, off));
            if (lane == 0) rmax[b_ * 10 + oc][wid] = m;
        }
    __syncthreads();
    if (t < 20) {
        float m = -3.4e38f;
#pragma unroll
        for (int wdx = 0; wdx < 8; wdx++) m = fmaxf(m, rmax[t][wdx]);
        int b_ = t / 10, oc = t - b_ * 10;
        g_m3[(size_t)(bb * 2 + b_) * 80 + r * 10 + oc] = m;
    }
}

// ---------------- rotateMax (groups of 8 consecutive channels) ----------------
__global__ void k_finalmax2(float* __restrict__ out)
{
    int i = blockIdx.x * blockDim.x + threadIdx.x;   // 2560 = 256 b x 10 groups
    if (i >= 2560) return;
    int b = i / 10, gp = i - b * 10;
    const float* p = g_m3 + b * 80 + gp * 8;
    float m = p[0];
#pragma unroll
    for (int k = 1; k < 8; k++) m = fmaxf(m, p[k]);
    out[i] = m;
}

// ---------------- launch ----------------
extern "C" void kernel_launch(void* const* d_in, const int* in_sizes, int n_in,
                              void* d_out, int out_size)
{
    const float* x  = (const float*)d_in[0];
    const float* w1 = (const float*)d_in[1];
    const float* g1 = (const float*)d_in[2];
    const float* b1 = (const float*)d_in[3];
    const float* w2 = (const float*)d_in[4];
    const float* g2 = (const float*)d_in[5];
    const float* b2 = (const float*)d_in[6];
    const float* w3 = (const float*)d_in[7];
    float* out = (float*)d_out;

    k_build<<<65, 256>>>(w1, w2, w3);
    k_conv1_statspool<<<dim3(256, 8), 256>>>(x);
    k_stats_final<<<6, 256>>>(g1, b1, 6, 1.f / 8388608.f);     // N = 256*8*64*64
    k_conv2<<<dim3(256, 8), 512>>>();                           // launch #4 -> ncu capture slot
    k_stats_final<<<16, 256>>>(g2, b2, 16, 1.f / 2097152.f);   // N = 256*8*32*32
    k_conv3<<<dim3(128, 8), 256>>>();
    k_finalmax2<<<10, 256>>>(out);
}

// round 12
// speedup vs baseline: 1.0017x; 1.0017x over previous
#include <cuda_runtime.h>

// ---------------- sizes ----------------
constexpr int B_ = 256;
constexpr int R_ = 8;
constexpr int C2 = 128;

// ---------------- scratch (device globals; allocation-free rule) ----------------
__device__ float g_sw1[48 * 1 * 5];
__device__ float g_sw2[128 * 48 * 5];
__device__ float g_sw3[80 * 128 * 5];
__device__ float g_p1[(size_t)B_ * 48 * 32 * 32];    // 50 MB  raw pooled conv1 (BN in conv2 loader)
__device__ float g_q2[(size_t)B_ * 128 * 16 * 16];   // 33.5 MB raw pooled conv2 (BN in conv3 loader)
__device__ float g_m3[B_ * 80];                      // conv3 spatial max per (b, ch)
__device__ float g_psum[B_ * R_ * 16];
__device__ float g_psq[B_ * R_ * 16];
__device__ float g_scale[C2];
__device__ float g_shift[C2];

// pad tables: top and left pads per rotation row (from reference L)
__device__ const int c_LT[8][3] = {{2,1,0},{2,1,1},{2,1,0},{1,1,1},{0,1,2},{0,1,2},{0,1,2},{1,1,1}};
__device__ const int c_LL[8][3] = {{0,1,2},{1,1,1},{2,1,0},{2,1,0},{2,1,0},{1,1,1},{0,1,2},{0,1,2}};

// Sparse tap offsets per rotation class (runtime; hoists to 5 regs).
// cls1 slot 4 is a dummy (weight is always 0 there by construction).
__device__ __forceinline__ void taps(int cls, int oy[5], int ox[5]) {
#pragma unroll
    for (int s = 0; s < 5; s++) {
        int a = 2 - s;
        if (cls == 0)      { oy[s] = a;                     ox[s] = -a; }
        else if (cls == 1) { oy[s] = (s < 4) ? (1 - s) : 0; ox[s] = 0;  }
        else if (cls == 2) { oy[s] = a;                     ox[s] = a;  }
        else               { oy[s] = 0;                     ox[s] = a;  }
    }
}

// ---------------- build sparse effective kernels ----------------
__global__ void k_build(const float* __restrict__ w1, const float* __restrict__ w2,
                        const float* __restrict__ w3)
{
    int idx = blockIdx.x * blockDim.x + threadIdx.x;
    const float* w; float* out;
    int oc, ic, icfull, ocper, g;
    if (idx < 48)                     { w = w1; out = g_sw1; oc = idx; ic = 0; icfull = 1;   ocper = 6;  g = 0;  }
    else if (idx < 48 + 6144)         { int p = idx - 48;        w = w2; out = g_sw2; oc = p / 48;  ic = p % 48;  icfull = 48;  ocper = 16; g = 6;  }
    else if (idx < 48 + 6144 + 10240) { int p = idx - 48 - 6144; w = w3; out = g_sw3; oc = p / 128; ic = p % 128; icfull = 128; ocper = 10; g = 16; }
    else return;

    int i  = oc / ocper;
    int co = oc % ocper;
    int i2 = (i + 4) & 7;
    int cls = i & 3;
    int sic = ic;
    if (g) {                     // rotateChannel applied i times
        int rin = ic / g, gg = ic - rin * g;
        sic = ((rin - i) & 7) * g + gg;
    }
    float acc[5] = {0.f, 0.f, 0.f, 0.f, 0.f};
#pragma unroll
    for (int j = 0; j < 3; j++) {
#pragma unroll
        for (int k = 0; k < 3; k++) {
            int dy = c_LT[i][j] + c_LT[i2][k];
            int dx = c_LL[i][j] + c_LL[i2][k];
            int slot = (cls == 1) ? (dy - 1) : ((cls == 3) ? dx : dy);
            float v = w[(co * icfull + sic) * 9 + j * 3 + k];
#pragma unroll
            for (int s = 0; s < 5; s++) if (slot == s) acc[s] += v;
        }
    }
#pragma unroll
    for (int s = 0; s < 5; s++) out[(oc * icfull + ic) * 5 + s] = acc[s];
}

// ======= conv1 single pass: conv + exact stats + raw pooled max -> p1 =======
__global__ __launch_bounds__(256, 2) void k_conv1_statspool(const float* __restrict__ x)
{
    __shared__ float s_in[68 * 68];
    __shared__ float rs[6][8], rq[6][8];
    int b = blockIdx.x, r = blockIdx.y, cls = r & 3;
    int t = threadIdx.x;
    const float* xb = x + (size_t)b * 4096;
    for (int i = t; i < 68 * 68; i += 256) {
        int yy = i / 68, xx = i - yy * 68;
        int gy = yy - 2, gx = xx - 2;
        float v = 0.f;
        if ((unsigned)gy < 64u && (unsigned)gx < 64u) v = xb[gy * 64 + gx];
        s_in[i] = v;
    }
    float w[6][5];
#pragma unroll
    for (int oc = 0; oc < 6; oc++)
#pragma unroll
        for (int s = 0; s < 5; s++) w[oc][s] = g_sw1[(r * 6 + oc) * 5 + s];
    int oy[5], ox[5]; taps(cls, oy, ox);
    int boff[5];
#pragma unroll
    for (int s = 0; s < 5; s++) boff[s] = oy[s] * 68 + ox[s];
    __syncthreads();

    int pr = t >> 3, pc0 = (t & 7) << 2;   // pooled: 32 rows x 32 cols, 4 cols/thread
    float ssum[6] = {0,0,0,0,0,0}, ssq[6] = {0,0,0,0,0,0};
    float mx[6][4];
#pragma unroll
    for (int oc = 0; oc < 6; oc++)
#pragma unroll
        for (int i = 0; i < 4; i++) mx[oc][i] = -3.4e38f;

#pragma unroll
    for (int i = 0; i < 4; i++) {
#pragma unroll
        for (int dy = 0; dy < 2; dy++) {
#pragma unroll
            for (int dx = 0; dx < 2; dx++) {
                int cy = 2 * pr + dy, cx = 2 * (pc0 + i) + dx;
                int base = (cy + 2) * 68 + cx + 2;
                float in5[5];
#pragma unroll
                for (int s = 0; s < 5; s++) in5[s] = s_in[base + boff[s]];
#pragma unroll
                for (int oc = 0; oc < 6; oc++) {
                    float a = 0.f;
#pragma unroll
                    for (int s = 0; s < 5; s++) a = fmaf(w[oc][s], in5[s], a);
                    mx[oc][i] = fmaxf(mx[oc][i], a);
                    ssum[oc] += a;
                    ssq[oc]  = fmaf(a, a, ssq[oc]);
                }
            }
        }
    }
#pragma unroll
    for (int oc = 0; oc < 6; oc++) {
        float4 o = make_float4(mx[oc][0], mx[oc][1], mx[oc][2], mx[oc][3]);
        *(float4*)&g_p1[((size_t)(b * 48 + r * 6 + oc)) * 1024 + pr * 32 + pc0] = o;
    }
    int lane = t & 31, wid = t >> 5;
#pragma unroll
    for (int oc = 0; oc < 6; oc++) {
        float s = ssum[oc], q = ssq[oc];
#pragma unroll
        for (int off = 16; off; off >>= 1) {
            s += __shfl_down_sync(0xffffffffu, s, off);
            q += __shfl_down_sync(0xffffffffu, q, off);
        }
        if (lane == 0) { rs[oc][wid] = s; rq[oc][wid] = q; }
    }
    __syncthreads();
    if (t < 6) {
        float S = 0.f, Q = 0.f;
#pragma unroll
        for (int wdx = 0; wdx < 8; wdx++) { S += rs[t][wdx]; Q += rq[t][wdx]; }
        int p = (b * 8 + r) * 6 + t;
        g_psum[p] = S; g_psq[p] = Q;
    }
}

// ---------------- parallel BN stats finalize ----------------
__global__ void k_stats_final(const float* __restrict__ gamma, const float* __restrict__ beta,
                              int Cc, float invN)
{
    int c = blockIdx.x;
    float S = 0.f, Q = 0.f;
    for (int i = threadIdx.x; i < 2048; i += 256) {
        S += g_psum[i * Cc + c];
        Q += g_psq[i * Cc + c];
    }
    __shared__ float ss[256], sq[256];
    int t = threadIdx.x;
    ss[t] = S; sq[t] = Q; __syncthreads();
    for (int st = 128; st > 0; st >>= 1) {
        if (t < st) { ss[t] += ss[t + st]; sq[t] += sq[t + st]; }
        __syncthreads();
    }
    if (t == 0) {
        float mean = ss[0] * invN;
        float var  = sq[0] * invN - mean * mean;
        float sc = gamma[c] / sqrtf(var + 1e-5f);
        float sh = beta[c] - mean * sc;
        for (int rr = 0; rr < R_; rr++) { g_scale[rr * Cc + c] = sc; g_shift[rr * Cc + c] = sh; }
    }
}

// ==== conv2: BN+ReLU in loader via smem-cached scales; 512 thr, scalar FFMA ====
__global__ __launch_bounds__(512, 2) void k_conv2()
{
    __shared__ float s_in[6][1296];                   // 31104 B (6-ic chunk, 36x36 halo)
    __shared__ __align__(16) float s_w[6][16][8];     // 3072 B
    __shared__ float rs[16][16], rq[16][16];          // 2048 B
    __shared__ float s_sc[48], s_sh[48];              // 384 B
    int b = blockIdx.x, r = blockIdx.y, cls = r & 3;
    int t = threadIdx.x;
    if (t < 48) { s_sc[t] = g_scale[t]; s_sh[t] = g_shift[t]; }
    int oy[5], ox[5]; taps(cls, oy, ox);
    int boff[5];
#pragma unroll
    for (int s = 0; s < 5; s++) boff[s] = oy[s] * 36 + ox[s];
    int row = t >> 4;           // 0..31 (warp w covers rows 2w, 2w+1)
    int x0  = (t & 15) << 1;    // 0..30
    int base = (row + 2) * 36 + x0 + 2;
    float acc[16][2];
#pragma unroll
    for (int o = 0; o < 16; o++) { acc[o][0] = 0.f; acc[o][1] = 0.f; }
    const float* pin = g_p1 + (size_t)b * 48 * 1024;
    const float* pw  = g_sw2 + (size_t)r * 16 * 48 * 5;
    __syncthreads();            // s_sc/s_sh visible before loader use
    for (int icc = 0; icc < 48; icc += 6) {
        for (int i = t; i < 6 * 1296; i += 512) {
            int ic = i / 1296; int rem = i - ic * 1296;
            int yy = rem / 36, xx = rem - yy * 36;
            int gy = yy - 2, gx = xx - 2;
            float v = 0.f;
            if ((unsigned)gy < 32u && (unsigned)gx < 32u) {
                float raw = pin[(icc + ic) * 1024 + gy * 32 + gx];
                v = fmaxf(0.f, fmaf(s_sc[icc + ic], raw, s_sh[icc + ic]));
            }
            s_in[ic][rem] = v;
        }
        if (t < 480) {          // 6 ic x 16 oc x 5 s
            int ic = t / 80; int rem = t - ic * 80; int oc = rem / 5; int s = rem - oc * 5;
            s_w[ic][oc][s] = pw[(oc * 48 + icc + ic) * 5 + s];
        }
        __syncthreads();
#pragma unroll 1
        for (int ic = 0; ic < 6; ic++) {
            float in5[5][2];
#pragma unroll
            for (int s = 0; s < 5; s++) {
                int off = base + boff[s];
                in5[s][0] = s_in[ic][off];
                in5[s][1] = s_in[ic][off + 1];
            }
#pragma unroll
            for (int oc = 0; oc < 16; oc++) {
                float4 w03 = *(const float4*)&s_w[ic][oc][0];
                float  w4  = s_w[ic][oc][4];
                float a0 = acc[oc][0], a1 = acc[oc][1];
                a0 = fmaf(w03.x, in5[0][0], a0);  a1 = fmaf(w03.x, in5[0][1], a1);
                a0 = fmaf(w03.y, in5[1][0], a0);  a1 = fmaf(w03.y, in5[1][1], a1);
                a0 = fmaf(w03.z, in5[2][0], a0);  a1 = fmaf(w03.z, in5[2][1], a1);
                a0 = fmaf(w03.w, in5[3][0], a0);  a1 = fmaf(w03.w, in5[3][1], a1);
                a0 = fmaf(w4,   in5[4][0], a0);  a1 = fmaf(w4,   in5[4][1], a1);
                acc[oc][0] = a0; acc[oc][1] = a1;
            }
        }
        __syncthreads();
    }
    // epilogue: fused exact stats + pooled raw 2x2 max (warp = rows 2w,2w+1)
    int lane = t & 31, wid = t >> 5;
    size_t qbase = (((size_t)b * 128) + r * 16) * 256 + wid * 16;
#pragma unroll
    for (int oc = 0; oc < 16; oc++) {
        float s = acc[oc][0] + acc[oc][1];
        float q = acc[oc][0] * acc[oc][0] + acc[oc][1] * acc[oc][1];
#pragma unroll
        for (int off = 16; off; off >>= 1) {
            s += __shfl_down_sync(0xffffffffu, s, off);
            q += __shfl_down_sync(0xffffffffu, q, off);
        }
        if (lane == 0) { rs[oc][wid] = s; rq[oc][wid] = q; }
        float m = fmaxf(acc[oc][0], acc[oc][1]);             // horizontal pair
        float o = fmaxf(m, __shfl_xor_sync(0xffffffffu, m, 16));  // row pair
        if (lane < 16) g_q2[qbase + (size_t)oc * 256 + lane] = o;
    }
    __syncthreads();
    if (t < 16) {
        float S = 0.f, Q = 0.f;
#pragma unroll
        for (int wdx = 0; wdx < 16; wdx++) { S += rs[t][wdx]; Q += rq[t][wdx]; }
        int p = (b * 8 + r) * 16 + t;
        g_psum[p] = S; g_psq[p] = Q;
    }
}

// ==== conv3: BN+ReLU in loader via smem-cached scales; 2 batches/block ====
__global__ __launch_bounds__(256, 4) void k_conv3()
{
    __shared__ float s_in[4][2][400];                 // 12800 B [ic][batch][20x20]
    __shared__ __align__(16) float s_w[4][10][8];     // 1280 B
    __shared__ float rmax[20][8];                     // 640 B
    __shared__ float s_sc[128], s_sh[128];            // 1024 B
    int bb = blockIdx.x, r = blockIdx.y, cls = r & 3; // bb: 0..127 (batch pairs)
    int t = threadIdx.x;
    if (t < 128) { s_sc[t] = g_scale[t]; s_sh[t] = g_shift[t]; }
    int oy[5], ox[5]; taps(cls, oy, ox);
    int boff[5];
#pragma unroll
    for (int s = 0; s < 5; s++) boff[s] = oy[s] * 20 + ox[s];
    int y = t >> 4, x = t & 15;
    int base = (y + 2) * 20 + x + 2;
    float acc[2][10];
#pragma unroll
    for (int b_ = 0; b_ < 2; b_++)
#pragma unroll
        for (int oc = 0; oc < 10; oc++) acc[b_][oc] = 0.f;
    const float* pw = g_sw3 + (size_t)r * 10 * 128 * 5;
    __syncthreads();            // s_sc/s_sh visible before loader use
    for (int icc = 0; icc < 128; icc += 4) {
        for (int i = t; i < 3200; i += 256) {
            int ic = i / 800; int rem = i - ic * 800;
            int b_ = rem / 400; int rem2 = rem - b_ * 400;
            int yy = rem2 / 20, xx = rem2 - yy * 20;
            int gy = yy - 2, gx = xx - 2;
            float v = 0.f;
            if ((unsigned)gy < 16u && (unsigned)gx < 16u) {
                float raw = g_q2[(((size_t)(bb * 2 + b_) * 128) + icc + ic) * 256 + gy * 16 + gx];
                v = fmaxf(0.f, fmaf(s_sc[icc + ic], raw, s_sh[icc + ic]));
            }
            s_in[ic][b_][rem2] = v;
        }
        if (t < 200) {          // 4 ic x 10 oc x 5 s
            int ic = t / 50; int rem = t - ic * 50; int oc = rem / 5; int s = rem - oc * 5;
            s_w[ic][oc][s] = pw[(oc * 128 + icc + ic) * 5 + s];
        }
        __syncthreads();
#pragma unroll 1
        for (int ic = 0; ic < 4; ic++) {
            float in5[5][2];
#pragma unroll
            for (int s = 0; s < 5; s++) {
                in5[s][0] = s_in[ic][0][base + boff[s]];
                in5[s][1] = s_in[ic][1][base + boff[s]];
            }
#pragma unroll
            for (int oc = 0; oc < 10; oc++) {
                float4 w03 = *(const float4*)&s_w[ic][oc][0];
                float  w4  = s_w[ic][oc][4];
#pragma unroll
                for (int b_ = 0; b_ < 2; b_++) {
                    float a = acc[b_][oc];
                    a = fmaf(w03.x, in5[0][b_], a);
                    a = fmaf(w03.y, in5[1][b_], a);
                    a = fmaf(w03.z, in5[2][b_], a);
                    a = fmaf(w03.w, in5[3][b_], a);
                    a = fmaf(w4,   in5[4][b_], a);
                    acc[b_][oc] = a;
                }
            }
        }
        __syncthreads();
    }
    // in-block spatial max per (b_, oc)
    int lane = t & 31, wid = t >> 5;
#pragma unroll
    for (int b_ = 0; b_ < 2; b_++)
#pragma unroll
        for (int oc = 0; oc < 10; oc++) {
            float m = acc[b_][oc];
#pragma unroll
            for (int off = 16; off; off >>= 1)
                m = fmaxf(m, __shfl_down_sync(0xffffffffu, m, off));
            if (lane == 0) rmax[b_ * 10 + oc][wid] = m;
        }
    __syncthreads();
    if (t < 20) {
        float m = -3.4e38f;
#pragma unroll
        for (int wdx = 0; wdx < 8; wdx++) m = fmaxf(m, rmax[t][wdx]);
        int b_ = t / 10, oc = t - b_ * 10;
        g_m3[(size_t)(bb * 2 + b_) * 80 + r * 10 + oc] = m;
    }
}

// ---------------- rotateMax (groups of 8 consecutive channels) ----------------
__global__ void k_finalmax2(float* __restrict__ out)
{
    int i = blockIdx.x * blockDim.x + threadIdx.x;   // 2560 = 256 b x 10 groups
    if (i >= 2560) return;
    int b = i / 10, gp = i - b * 10;
    const float* p = g_m3 + b * 80 + gp * 8;
    float m = p[0];
#pragma unroll
    for (int k = 1; k < 8; k++) m = fmaxf(m, p[k]);
    out[i] = m;
}

// ---------------- launch ----------------
extern "C" void kernel_launch(void* const* d_in, const int* in_sizes, int n_in,
                              void* d_out, int out_size)
{
    const float* x  = (const float*)d_in[0];
    const float* w1 = (const float*)d_in[1];
    const float* g1 = (const float*)d_in[2];
    const float* b1 = (const float*)d_in[3];
    const float* w2 = (const float*)d_in[4];
    const float* g2 = (const float*)d_in[5];
    const float* b2 = (const float*)d_in[6];
    const float* w3 = (const float*)d_in[7];
    float* out = (float*)d_out;

    k_build<<<65, 256>>>(w1, w2, w3);
    k_conv1_statspool<<<dim3(256, 8), 256>>>(x);
    k_stats_final<<<6, 256>>>(g1, b1, 6, 1.f / 8388608.f);     // N = 256*8*64*64
    k_conv2<<<dim3(256, 8), 512>>>();                           // launch #4 -> ncu capture slot
    k_stats_final<<<16, 256>>>(g2, b2, 16, 1.f / 2097152.f);   // N = 256*8*32*32
    k_conv3<<<dim3(128, 8), 256>>>();
    k_finalmax2<<<10, 256>>>(out);
}

// round 13
// speedup vs baseline: 1.1297x; 1.1279x over previous
#include <cuda_runtime.h>

// ---------------- sizes ----------------
constexpr int B_ = 256;
constexpr int R_ = 8;
constexpr int C2 = 128;

// ---------------- scratch (device globals; allocation-free rule) ----------------
__device__ float g_sw1[48 * 1 * 5];
__device__ float g_sw2[128 * 48 * 5];
__device__ float g_sw3[80 * 128 * 5];
__device__ float g_p1[(size_t)B_ * 48 * 32 * 32];    // 50 MB  raw pooled conv1 -> BN'd in place
__device__ float g_q2[(size_t)B_ * 128 * 16 * 16];   // 33.5 MB pooled raw max of conv2
__device__ float g_p2[(size_t)B_ * 128 * 16 * 16];   // 33.5 MB
__device__ float g_m3[B_ * 80];                      // conv3 spatial max per (b, ch)
__device__ float g_psum[B_ * R_ * 16];
__device__ float g_psq[B_ * R_ * 16];
__device__ float g_scale[C2];
__device__ float g_shift[C2];

// pad tables: top and left pads per rotation row (from reference L)
__device__ const int c_LT[8][3] = {{2,1,0},{2,1,1},{2,1,0},{1,1,1},{0,1,2},{0,1,2},{0,1,2},{1,1,1}};
__device__ const int c_LL[8][3] = {{0,1,2},{1,1,1},{2,1,0},{2,1,0},{2,1,0},{1,1,1},{0,1,2},{0,1,2}};

// Sparse tap offsets per rotation class (runtime; hoists to 5 regs).
// cls1 slot 4 is a dummy (weight is always 0 there by construction).
__device__ __forceinline__ void taps(int cls, int oy[5], int ox[5]) {
#pragma unroll
    for (int s = 0; s < 5; s++) {
        int a = 2 - s;
        if (cls == 0)      { oy[s] = a;                     ox[s] = -a; }
        else if (cls == 1) { oy[s] = (s < 4) ? (1 - s) : 0; ox[s] = 0;  }
        else if (cls == 2) { oy[s] = a;                     ox[s] = a;  }
        else               { oy[s] = 0;                     ox[s] = a;  }
    }
}

// ---------------- build sparse effective kernels ----------------
__global__ void k_build(const float* __restrict__ w1, const float* __restrict__ w2,
                        const float* __restrict__ w3)
{
    int idx = blockIdx.x * blockDim.x + threadIdx.x;
    const float* w; float* out;
    int oc, ic, icfull, ocper, g;
    if (idx < 48)                     { w = w1; out = g_sw1; oc = idx; ic = 0; icfull = 1;   ocper = 6;  g = 0;  }
    else if (idx < 48 + 6144)         { int p = idx - 48;        w = w2; out = g_sw2; oc = p / 48;  ic = p % 48;  icfull = 48;  ocper = 16; g = 6;  }
    else if (idx < 48 + 6144 + 10240) { int p = idx - 48 - 6144; w = w3; out = g_sw3; oc = p / 128; ic = p % 128; icfull = 128; ocper = 10; g = 16; }
    else return;

    int i  = oc / ocper;
    int co = oc % ocper;
    int i2 = (i + 4) & 7;
    int cls = i & 3;
    int sic = ic;
    if (g) {                     // rotateChannel applied i times
        int rin = ic / g, gg = ic - rin * g;
        sic = ((rin - i) & 7) * g + gg;
    }
    float acc[5] = {0.f, 0.f, 0.f, 0.f, 0.f};
#pragma unroll
    for (int j = 0; j < 3; j++) {
#pragma unroll
        for (int k = 0; k < 3; k++) {
            int dy = c_LT[i][j] + c_LT[i2][k];
            int dx = c_LL[i][j] + c_LL[i2][k];
            int slot = (cls == 1) ? (dy - 1) : ((cls == 3) ? dx : dy);
            float v = w[(co * icfull + sic) * 9 + j * 3 + k];
#pragma unroll
            for (int s = 0; s < 5; s++) if (slot == s) acc[s] += v;
        }
    }
#pragma unroll
    for (int s = 0; s < 5; s++) out[(oc * icfull + ic) * 5 + s] = acc[s];
}

// ======= conv1 single pass: conv + exact stats + raw pooled max -> p1 =======
__global__ __launch_bounds__(256, 2) void k_conv1_statspool(const float* __restrict__ x)
{
    __shared__ float s_in[68 * 68];
    __shared__ float rs[6][8], rq[6][8];
    int b = blockIdx.x, r = blockIdx.y, cls = r & 3;
    int t = threadIdx.x;
    const float* xb = x + (size_t)b * 4096;
    for (int i = t; i < 68 * 68; i += 256) {
        int yy = i / 68, xx = i - yy * 68;
        int gy = yy - 2, gx = xx - 2;
        float v = 0.f;
        if ((unsigned)gy < 64u && (unsigned)gx < 64u) v = xb[gy * 64 + gx];
        s_in[i] = v;
    }
    float w[6][5];
#pragma unroll
    for (int oc = 0; oc < 6; oc++)
#pragma unroll
        for (int s = 0; s < 5; s++) w[oc][s] = g_sw1[(r * 6 + oc) * 5 + s];
    int oy[5], ox[5]; taps(cls, oy, ox);
    int boff[5];
#pragma unroll
    for (int s = 0; s < 5; s++) boff[s] = oy[s] * 68 + ox[s];
    __syncthreads();

    int pr = t >> 3, pc0 = (t & 7) << 2;   // pooled: 32 rows x 32 cols, 4 cols/thread
    float ssum[6] = {0,0,0,0,0,0}, ssq[6] = {0,0,0,0,0,0};
    float mx[6][4];
#pragma unroll
    for (int oc = 0; oc < 6; oc++)
#pragma unroll
        for (int i = 0; i < 4; i++) mx[oc][i] = -3.4e38f;

#pragma unroll
    for (int i = 0; i < 4; i++) {
#pragma unroll
        for (int dy = 0; dy < 2; dy++) {
#pragma unroll
            for (int dx = 0; dx < 2; dx++) {
                int cy = 2 * pr + dy, cx = 2 * (pc0 + i) + dx;
                int base = (cy + 2) * 68 + cx + 2;
                float in5[5];
#pragma unroll
                for (int s = 0; s < 5; s++) in5[s] = s_in[base + boff[s]];
#pragma unroll
                for (int oc = 0; oc < 6; oc++) {
                    float a = 0.f;
#pragma unroll
                    for (int s = 0; s < 5; s++) a = fmaf(w[oc][s], in5[s], a);
                    mx[oc][i] = fmaxf(mx[oc][i], a);
                    ssum[oc] += a;
                    ssq[oc]  = fmaf(a, a, ssq[oc]);
                }
            }
        }
    }
#pragma unroll
    for (int oc = 0; oc < 6; oc++) {
        float4 o = make_float4(mx[oc][0], mx[oc][1], mx[oc][2], mx[oc][3]);
        *(float4*)&g_p1[((size_t)(b * 48 + r * 6 + oc)) * 1024 + pr * 32 + pc0] = o;
    }
    int lane = t & 31, wid = t >> 5;
#pragma unroll
    for (int oc = 0; oc < 6; oc++) {
        float s = ssum[oc], q = ssq[oc];
#pragma unroll
        for (int off = 16; off; off >>= 1) {
            s += __shfl_down_sync(0xffffffffu, s, off);
            q += __shfl_down_sync(0xffffffffu, q, off);
        }
        if (lane == 0) { rs[oc][wid] = s; rq[oc][wid] = q; }
    }
    __syncthreads();
    if (t < 6) {
        float S = 0.f, Q = 0.f;
#pragma unroll
        for (int wdx = 0; wdx < 8; wdx++) { S += rs[t][wdx]; Q += rq[t][wdx]; }
        int p = (b * 8 + r) * 6 + t;
        g_psum[p] = S; g_psq[p] = Q;
    }
}

// ---------------- parallel BN stats finalize ----------------
__global__ void k_stats_final(const float* __restrict__ gamma, const float* __restrict__ beta,
                              int Cc, float invN)
{
    int c = blockIdx.x;
    float S = 0.f, Q = 0.f;
    for (int i = threadIdx.x; i < 2048; i += 256) {
        S += g_psum[i * Cc + c];
        Q += g_psq[i * Cc + c];
    }
    __shared__ float ss[256], sq[256];
    int t = threadIdx.x;
    ss[t] = S; sq[t] = Q; __syncthreads();
    for (int st = 128; st > 0; st >>= 1) {
        if (t < st) { ss[t] += ss[t + st]; sq[t] += sq[t + st]; }
        __syncthreads();
    }
    if (t == 0) {
        float mean = ss[0] * invN;
        float var  = sq[0] * invN - mean * mean;
        float sc = gamma[c] / sqrtf(var + 1e-5f);
        float sh = beta[c] - mean * sc;
        for (int rr = 0; rr < R_; rr++) { g_scale[rr * Cc + c] = sc; g_shift[rr * Cc + c] = sh; }
    }
}

// ---------------- BN + ReLU elementwise (both stages) ----------------
__global__ void k_bnrelu(const float* __restrict__ src, float* __restrict__ dst,
                         int CH, int f4_shift)
{
    int idx = blockIdx.x * 256 + threadIdx.x;
    int plane = idx >> f4_shift;
    int ch = plane % CH;
    float sc = g_scale[ch], sh = g_shift[ch];
    size_t p = (size_t)idx << 2;
    float4 v = *(const float4*)&src[p];
    float4 o;
    o.x = fmaxf(0.f, fmaf(sc, v.x, sh));
    o.y = fmaxf(0.f, fmaf(sc, v.y, sh));
    o.z = fmaxf(0.f, fmaf(sc, v.z, sh));
    o.w = fmaxf(0.f, fmaf(sc, v.w, sh));
    *(float4*)&dst[p] = o;
}

// ======== conv2: 256 threads, 4px x 16oc/thread, scalar FFMA ========
__global__ __launch_bounds__(256, 2) void k_conv2()
{
    __shared__ float s_in[6][1296];                   // 31104 B (6-ic chunk, 36x36 halo)
    __shared__ __align__(16) float s_w[6][16][8];     // 3072 B
    __shared__ float rs[16][8], rq[16][8];            // 512 B
    int b = blockIdx.x, r = blockIdx.y, cls = r & 3;
    int t = threadIdx.x;
    int oy[5], ox[5]; taps(cls, oy, ox);
    int boff[5];
#pragma unroll
    for (int s = 0; s < 5; s++) boff[s] = oy[s] * 36 + ox[s];
    int row = t >> 3;          // 0..31
    int x0  = (t & 7) << 2;    // 0..28
    int base = (row + 2) * 36 + x0 + 2;
    float acc[16][4];
#pragma unroll
    for (int o = 0; o < 16; o++)
#pragma unroll
        for (int i = 0; i < 4; i++) acc[o][i] = 0.f;
    const float* pin = g_p1 + (size_t)b * 48 * 1024;
    const float* pw  = g_sw2 + (size_t)r * 16 * 48 * 5;
    for (int icc = 0; icc < 48; icc += 6) {
        for (int i = t; i < 6 * 1296; i += 256) {
            int ic = i / 1296; int rem = i - ic * 1296;
            int yy = rem / 36, xx = rem - yy * 36;
            int gy = yy - 2, gx = xx - 2;
            float v = 0.f;
            if ((unsigned)gy < 32u && (unsigned)gx < 32u) v = pin[(icc + ic) * 1024 + gy * 32 + gx];
            s_in[ic][rem] = v;
        }
        for (int i = t; i < 480; i += 256) {          // 6 ic x 16 oc x 5 s
            int ic = i / 80; int rem = i - ic * 80; int oc = rem / 5; int s = rem - oc * 5;
            s_w[ic][oc][s] = pw[(oc * 48 + icc + ic) * 5 + s];
        }
        __syncthreads();
#pragma unroll 1
        for (int ic = 0; ic < 6; ic++) {
            float inv[5][4];
#pragma unroll
            for (int s = 0; s < 5; s++) {
                int off = base + boff[s];
#pragma unroll
                for (int i = 0; i < 4; i++) inv[s][i] = s_in[ic][off + i];
            }
#pragma unroll
            for (int oc = 0; oc < 16; oc++) {
                float4 w03 = *(const float4*)&s_w[ic][oc][0];
                float  w4  = s_w[ic][oc][4];
#pragma unroll
                for (int i = 0; i < 4; i++) {
                    float a = acc[oc][i];
                    a = fmaf(w03.x, inv[0][i], a);
                    a = fmaf(w03.y, inv[1][i], a);
                    a = fmaf(w03.z, inv[2][i], a);
                    a = fmaf(w03.w, inv[3][i], a);
                    a = fmaf(w4,   inv[4][i], a);
                    acc[oc][i] = a;
                }
            }
        }
        __syncthreads();
    }
    // epilogue: fused exact stats + pooled raw 2x2 max (lanes 8 apart = row pair)
    int lane = t & 31, wid = t >> 5;
    int prow = row >> 1;
    int pcol = (t & 7) << 1;
    size_t qbase = (((size_t)b * 128) + r * 16) * 256 + prow * 16 + pcol;
#pragma unroll
    for (int oc = 0; oc < 16; oc++) {
        float s = acc[oc][0] + acc[oc][1] + acc[oc][2] + acc[oc][3];
        float q = acc[oc][0] * acc[oc][0] + acc[oc][1] * acc[oc][1]
                + acc[oc][2] * acc[oc][2] + acc[oc][3] * acc[oc][3];
#pragma unroll
        for (int off = 16; off; off >>= 1) {
            s += __shfl_down_sync(0xffffffffu, s, off);
            q += __shfl_down_sync(0xffffffffu, q, off);
        }
        if (lane == 0) { rs[oc][wid] = s; rq[oc][wid] = q; }
        float m0 = fmaxf(acc[oc][0], acc[oc][1]);
        float m1 = fmaxf(acc[oc][2], acc[oc][3]);
        float o0 = fmaxf(m0, __shfl_xor_sync(0xffffffffu, m0, 8));
        float o1 = fmaxf(m1, __shfl_xor_sync(0xffffffffu, m1, 8));
        if ((lane & 8) == 0)
            *(float2*)&g_q2[qbase + (size_t)oc * 256] = make_float2(o0, o1);
    }
    __syncthreads();
    if (t < 16) {
        float S = 0.f, Q = 0.f;
#pragma unroll
        for (int wdx = 0; wdx < 8; wdx++) { S += rs[t][wdx]; Q += rq[t][wdx]; }
        int p = (b * 8 + r) * 16 + t;
        g_psum[p] = S; g_psq[p] = Q;
    }
}

// ======== conv3: 2 batches/block, scalar FFMA (R10) -> spatial max ========
__global__ __launch_bounds__(256, 4) void k_conv3()
{
    __shared__ float s_in[4][2][400];                 // 12800 B [ic][batch][20x20]
    __shared__ __align__(16) float s_w[4][10][8];     // 1280 B
    __shared__ float rmax[20][8];                     // 640 B
    int bb = blockIdx.x, r = blockIdx.y, cls = r & 3; // bb: 0..127 (batch pairs)
    int t = threadIdx.x;
    int oy[5], ox[5]; taps(cls, oy, ox);
    int boff[5];
#pragma unroll
    for (int s = 0; s < 5; s++) boff[s] = oy[s] * 20 + ox[s];
    int y = t >> 4, x = t & 15;
    int base = (y + 2) * 20 + x + 2;
    float acc[2][10];
#pragma unroll
    for (int b_ = 0; b_ < 2; b_++)
#pragma unroll
        for (int oc = 0; oc < 10; oc++) acc[b_][oc] = 0.f;
    const float* pw = g_sw3 + (size_t)r * 10 * 128 * 5;
    for (int icc = 0; icc < 128; icc += 4) {
        for (int i = t; i < 3200; i += 256) {
            int ic = i / 800; int rem = i - ic * 800;
            int b_ = rem / 400; int rem2 = rem - b_ * 400;
            int yy = rem2 / 20, xx = rem2 - yy * 20;
            int gy = yy - 2, gx = xx - 2;
            float v = 0.f;
            if ((unsigned)gy < 16u && (unsigned)gx < 16u)
                v = g_p2[(((size_t)(bb * 2 + b_) * 128) + icc + ic) * 256 + gy * 16 + gx];
            s_in[ic][b_][rem2] = v;
        }
        if (t < 200) {          // 4 ic x 10 oc x 5 s
            int ic = t / 50; int rem = t - ic * 50; int oc = rem / 5; int s = rem - oc * 5;
            s_w[ic][oc][s] = pw[(oc * 128 + icc + ic) * 5 + s];
        }
        __syncthreads();
#pragma unroll 1
        for (int ic = 0; ic < 4; ic++) {
            float in5[5][2];
#pragma unroll
            for (int s = 0; s < 5; s++) {
                in5[s][0] = s_in[ic][0][base + boff[s]];
                in5[s][1] = s_in[ic][1][base + boff[s]];
            }
#pragma unroll
            for (int oc = 0; oc < 10; oc++) {
                float4 w03 = *(const float4*)&s_w[ic][oc][0];
                float  w4  = s_w[ic][oc][4];
#pragma unroll
                for (int b_ = 0; b_ < 2; b_++) {
                    float a = acc[b_][oc];
                    a = fmaf(w03.x, in5[0][b_], a);
                    a = fmaf(w03.y, in5[1][b_], a);
                    a = fmaf(w03.z, in5[2][b_], a);
                    a = fmaf(w03.w, in5[3][b_], a);
                    a = fmaf(w4,   in5[4][b_], a);
                    acc[b_][oc] = a;
                }
            }
        }
        __syncthreads();
    }
    // in-block spatial max per (b_, oc)
    int lane = t & 31, wid = t >> 5;
#pragma unroll
    for (int b_ = 0; b_ < 2; b_++)
#pragma unroll
        for (int oc = 0; oc < 10; oc++) {
            float m = acc[b_][oc];
#pragma unroll
            for (int off = 16; off; off >>= 1)
                m = fmaxf(m, __shfl_down_sync(0xffffffffu, m, off));
            if (lane == 0) rmax[b_ * 10 + oc][wid] = m;
        }
    __syncthreads();
    if (t < 20) {
        float m = -3.4e38f;
#pragma unroll
        for (int wdx = 0; wdx < 8; wdx++) m = fmaxf(m, rmax[t][wdx]);
        int b_ = t / 10, oc = t - b_ * 10;
        g_m3[(size_t)(bb * 2 + b_) * 80 + r * 10 + oc] = m;
    }
}

// ---------------- rotateMax (groups of 8 consecutive channels) ----------------
__global__ void k_finalmax2(float* __restrict__ out)
{
    int i = blockIdx.x * blockDim.x + threadIdx.x;   // 2560 = 256 b x 10 groups
    if (i >= 2560) return;
    int b = i / 10, gp = i - b * 10;
    const float* p = g_m3 + b * 80 + gp * 8;
    float m = p[0];
#pragma unroll
    for (int k = 1; k < 8; k++) m = fmaxf(m, p[k]);
    out[i] = m;
}

// ---------------- launch ----------------
extern "C" void kernel_launch(void* const* d_in, const int* in_sizes, int n_in,
                              void* d_out, int out_size)
{
    const float* x  = (const float*)d_in[0];
    const float* w1 = (const float*)d_in[1];
    const float* g1 = (const float*)d_in[2];
    const float* b1 = (const float*)d_in[3];
    const float* w2 = (const float*)d_in[4];
    const float* g2 = (const float*)d_in[5];
    const float* b2 = (const float*)d_in[6];
    const float* w3 = (const float*)d_in[7];
    float* out = (float*)d_out;

    float *pp1, *pq2, *pp2;
    cudaGetSymbolAddress((void**)&pp1, g_p1);
    cudaGetSymbolAddress((void**)&pq2, g_q2);
    cudaGetSymbolAddress((void**)&pp2, g_p2);

    k_build<<<65, 256>>>(w1, w2, w3);
    k_conv1_statspool<<<dim3(256, 8), 256>>>(x);
    k_stats_final<<<6, 256>>>(g1, b1, 6, 1.f / 8388608.f);     // N = 256*8*64*64
    k_bnrelu<<<12288, 256>>>(pp1, pp1, 48, 8);                 // p1 in place (256 f4/plane)
    k_conv2<<<dim3(256, 8), 256>>>();
    k_stats_final<<<16, 256>>>(g2, b2, 16, 1.f / 2097152.f);   // N = 256*8*32*32
    k_bnrelu<<<8192, 256>>>(pq2, pp2, 128, 6);                 // q2 -> p2 (64 f4/plane)
    k_conv3<<<dim3(128, 8), 256>>>();
    k_finalmax2<<<10, 256>>>(out);
}

// round 15
// speedup vs baseline: 1.3949x; 1.2347x over previous
#include <cuda_runtime.h>

// ---------------- sizes ----------------
constexpr int B_ = 256;
constexpr int R_ = 8;
constexpr int C2 = 128;

// ---------------- scratch (device globals; allocation-free rule) ----------------
__device__ float g_sw1[48 * 1 * 5];
__device__ float g_sw2[128 * 48 * 5];
__device__ float g_sw3[80 * 128 * 5];
__device__ float g_p1[(size_t)B_ * 48 * 32 * 32];    // 50 MB  raw pooled conv1 -> BN'd in place
__device__ float g_q2[(size_t)B_ * 128 * 16 * 16];   // 33.5 MB pooled raw max of conv2
__device__ float g_p2[(size_t)B_ * 128 * 16 * 16];   // 33.5 MB
__device__ float g_m3[B_ * 80];                      // conv3 spatial max per (b, ch)
__device__ float g_psum[B_ * R_ * 16];
__device__ float g_psq[B_ * R_ * 16];
__device__ float g_scale[C2];
__device__ float g_shift[C2];

// pad tables: top and left pads per rotation row (from reference L)
__device__ const int c_LT[8][3] = {{2,1,0},{2,1,1},{2,1,0},{1,1,1},{0,1,2},{0,1,2},{0,1,2},{1,1,1}};
__device__ const int c_LL[8][3] = {{0,1,2},{1,1,1},{2,1,0},{2,1,0},{2,1,0},{1,1,1},{0,1,2},{0,1,2}};

// Sparse tap offsets per rotation class (runtime; hoists to regs).
// cls1 slot 4 is a dummy (weight is always 0 there by construction).
__device__ __forceinline__ void taps(int cls, int oy[5], int ox[5]) {
#pragma unroll
    for (int s = 0; s < 5; s++) {
        int a = 2 - s;
        if (cls == 0)      { oy[s] = a;                     ox[s] = -a; }
        else if (cls == 1) { oy[s] = (s < 4) ? (1 - s) : 0; ox[s] = 0;  }
        else if (cls == 2) { oy[s] = a;                     ox[s] = a;  }
        else               { oy[s] = 0;                     ox[s] = a;  }
    }
}

// ---------------- tf32 helpers ----------------
__device__ __forceinline__ unsigned to_tf32(float f) {
    unsigned u; asm("cvt.rna.tf32.f32 %0, %1;" : "=r"(u) : "f"(f)); return u;
}
__device__ __forceinline__ void mma_tf32(float* c, unsigned a0, unsigned a1,
                                         unsigned a2, unsigned a3,
                                         unsigned b0, unsigned b1) {
    asm("mma.sync.aligned.m16n8k8.row.col.f32.tf32.tf32.f32 "
        "{%0,%1,%2,%3}, {%4,%5,%6,%7}, {%8,%9}, {%0,%1,%2,%3};"
        : "+f"(c[0]), "+f"(c[1]), "+f"(c[2]), "+f"(c[3])
        : "r"(a0), "r"(a1), "r"(a2), "r"(a3), "r"(b0), "r"(b1));
}

// ---------------- build sparse effective kernels ----------------
__global__ void k_build(const float* __restrict__ w1, const float* __restrict__ w2,
                        const float* __restrict__ w3)
{
    int idx = blockIdx.x * blockDim.x + threadIdx.x;
    const float* w; float* out;
    int oc, ic, icfull, ocper, g;
    if (idx < 48)                     { w = w1; out = g_sw1; oc = idx; ic = 0; icfull = 1;   ocper = 6;  g = 0;  }
    else if (idx < 48 + 6144)         { int p = idx - 48;        w = w2; out = g_sw2; oc = p / 48;  ic = p % 48;  icfull = 48;  ocper = 16; g = 6;  }
    else if (idx < 48 + 6144 + 10240) { int p = idx - 48 - 6144; w = w3; out = g_sw3; oc = p / 128; ic = p % 128; icfull = 128; ocper = 10; g = 16; }
    else return;

    int i  = oc / ocper;
    int co = oc % ocper;
    int i2 = (i + 4) & 7;
    int cls = i & 3;
    int sic = ic;
    if (g) {                     // rotateChannel applied i times
        int rin = ic / g, gg = ic - rin * g;
        sic = ((rin - i) & 7) * g + gg;
    }
    float acc[5] = {0.f, 0.f, 0.f, 0.f, 0.f};
#pragma unroll
    for (int j = 0; j < 3; j++) {
#pragma unroll
        for (int k = 0; k < 3; k++) {
            int dy = c_LT[i][j] + c_LT[i2][k];
            int dx = c_LL[i][j] + c_LL[i2][k];
            int slot = (cls == 1) ? (dy - 1) : ((cls == 3) ? dx : dy);
            float v = w[(co * icfull + sic) * 9 + j * 3 + k];
#pragma unroll
            for (int s = 0; s < 5; s++) if (slot == s) acc[s] += v;
        }
    }
#pragma unroll
    for (int s = 0; s < 5; s++) out[(oc * icfull + ic) * 5 + s] = acc[s];
}

// ======= conv1 single pass: conv + exact stats + raw pooled max -> p1 =======
__global__ __launch_bounds__(256, 2) void k_conv1_statspool(const float* __restrict__ x)
{
    __shared__ float s_in[68 * 68];
    __shared__ float rs[6][8], rq[6][8];
    int b = blockIdx.x, r = blockIdx.y, cls = r & 3;
    int t = threadIdx.x;
    const float* xb = x + (size_t)b * 4096;
    for (int i = t; i < 68 * 68; i += 256) {
        int yy = i / 68, xx = i - yy * 68;
        int gy = yy - 2, gx = xx - 2;
        float v = 0.f;
        if ((unsigned)gy < 64u && (unsigned)gx < 64u) v = xb[gy * 64 + gx];
        s_in[i] = v;
    }
    float w[6][5];
#pragma unroll
    for (int oc = 0; oc < 6; oc++)
#pragma unroll
        for (int s = 0; s < 5; s++) w[oc][s] = g_sw1[(r * 6 + oc) * 5 + s];
    int oy[5], ox[5]; taps(cls, oy, ox);
    int boff[5];
#pragma unroll
    for (int s = 0; s < 5; s++) boff[s] = oy[s] * 68 + ox[s];
    __syncthreads();

    int pr = t >> 3, pc0 = (t & 7) << 2;   // pooled: 32 rows x 32 cols, 4 cols/thread
    float ssum[6] = {0,0,0,0,0,0}, ssq[6] = {0,0,0,0,0,0};
    float mx[6][4];
#pragma unroll
    for (int oc = 0; oc < 6; oc++)
#pragma unroll
        for (int i = 0; i < 4; i++) mx[oc][i] = -3.4e38f;

#pragma unroll
    for (int i = 0; i < 4; i++) {
#pragma unroll
        for (int dy = 0; dy < 2; dy++) {
#pragma unroll
            for (int dx = 0; dx < 2; dx++) {
                int cy = 2 * pr + dy, cx = 2 * (pc0 + i) + dx;
                int base = (cy + 2) * 68 + cx + 2;
                float in5[5];
#pragma unroll
                for (int s = 0; s < 5; s++) in5[s] = s_in[base + boff[s]];
#pragma unroll
                for (int oc = 0; oc < 6; oc++) {
                    float a = 0.f;
#pragma unroll
                    for (int s = 0; s < 5; s++) a = fmaf(w[oc][s], in5[s], a);
                    mx[oc][i] = fmaxf(mx[oc][i], a);
                    ssum[oc] += a;
                    ssq[oc]  = fmaf(a, a, ssq[oc]);
                }
            }
        }
    }
#pragma unroll
    for (int oc = 0; oc < 6; oc++) {
        float4 o = make_float4(mx[oc][0], mx[oc][1], mx[oc][2], mx[oc][3]);
        *(float4*)&g_p1[((size_t)(b * 48 + r * 6 + oc)) * 1024 + pr * 32 + pc0] = o;
    }
    int lane = t & 31, wid = t >> 5;
#pragma unroll
    for (int oc = 0; oc < 6; oc++) {
        float s = ssum[oc], q = ssq[oc];
#pragma unroll
        for (int off = 16; off; off >>= 1) {
            s += __shfl_down_sync(0xffffffffu, s, off);
            q += __shfl_down_sync(0xffffffffu, q, off);
        }
        if (lane == 0) { rs[oc][wid] = s; rq[oc][wid] = q; }
    }
    __syncthreads();
    if (t < 6) {
        float S = 0.f, Q = 0.f;
#pragma unroll
        for (int wdx = 0; wdx < 8; wdx++) { S += rs[t][wdx]; Q += rq[t][wdx]; }
        int p = (b * 8 + r) * 6 + t;
        g_psum[p] = S; g_psq[p] = Q;
    }
}

// ---------------- parallel BN stats finalize ----------------
__global__ void k_stats_final(const float* __restrict__ gamma, const float* __restrict__ beta,
                              int Cc, float invN)
{
    int c = blockIdx.x;
    float S = 0.f, Q = 0.f;
    for (int i = threadIdx.x; i < 2048; i += 256) {
        S += g_psum[i * Cc + c];
        Q += g_psq[i * Cc + c];
    }
    __shared__ float ss[256], sq[256];
    int t = threadIdx.x;
    ss[t] = S; sq[t] = Q; __syncthreads();
    for (int st = 128; st > 0; st >>= 1) {
        if (t < st) { ss[t] += ss[t + st]; sq[t] += sq[t + st]; }
        __syncthreads();
    }
    if (t == 0) {
        float mean = ss[0] * invN;
        float var  = sq[0] * invN - mean * mean;
        float sc = gamma[c] / sqrtf(var + 1e-5f);
        float sh = beta[c] - mean * sc;
        for (int rr = 0; rr < R_; rr++) { g_scale[rr * Cc + c] = sc; g_shift[rr * Cc + c] = sh; }
    }
}

// ---------------- BN + ReLU elementwise (both stages) ----------------
__global__ void k_bnrelu(const float* __restrict__ src, float* __restrict__ dst,
                         int CH, int f4_shift)
{
    int idx = blockIdx.x * 256 + threadIdx.x;
    int plane = idx >> f4_shift;
    int ch = plane % CH;
    float sc = g_scale[ch], sh = g_shift[ch];
    size_t p = (size_t)idx << 2;
    float4 v = *(const float4*)&src[p];
    float4 o;
    o.x = fmaxf(0.f, fmaf(sc, v.x, sh));
    o.y = fmaxf(0.f, fmaf(sc, v.y, sh));
    o.z = fmaxf(0.f, fmaf(sc, v.z, sh));
    o.w = fmaxf(0.f, fmaf(sc, v.w, sh));
    *(float4*)&dst[p] = o;
}

// ======== conv2: tf32 implicit GEMM via mma.m16n8k8 ========
// Per (b, r): D[16 oc][1024 px] = sum_k A[oc][k] * B[k][px], k = (ic, s).
// 8 chunks of 6 ic (K=30 padded to 32 -> 4 k-tiles of 8 per chunk).
// Warp w owns pixel rows 4w..4w+3; 16 n-tiles of 8 consecutive cols each.
__global__ __launch_bounds__(256, 2) void k_conv2()
{
    __shared__ unsigned s_in[6 * 1332];     // tf32 bits; 36 rows x stride-37 per ic
    __shared__ unsigned s_w[32][16];        // tf32 bits; [k][oc]
    __shared__ float rs[16][8], rq[16][8];
    int b = blockIdx.x, r = blockIdx.y, cls = r & 3;
    int t = threadIdx.x;
    int lane = t & 31, wid = t >> 5;
    int la = lane & 3, g = lane >> 2;
    int oy[5], ox[5]; taps(cls, oy, ox);
    // per-(k-tile, half) smem offsets for B rows: k = kt*8 + la + h*4
    int koff[4][2];
#pragma unroll
    for (int kt = 0; kt < 4; kt++)
#pragma unroll
        for (int h = 0; h < 2; h++) {
            int k = kt * 8 + la + h * 4;
            if (k < 30) {
                int ic = k / 5, s = k - ic * 5;
                koff[kt][h] = ic * 1332 + oy[s] * 37 + ox[s];
            } else koff[kt][h] = 0;    // dummy row: weight is 0
        }
    float acc[16][4];
#pragma unroll
    for (int nt = 0; nt < 16; nt++)
#pragma unroll
        for (int i = 0; i < 4; i++) acc[nt][i] = 0.f;

    const float* pin = g_p1 + (size_t)b * 48 * 1024;
    const float* pw  = g_sw2 + (size_t)r * 16 * 48 * 5;
    for (int icc = 0; icc < 48; icc += 6) {
        for (int i = t; i < 6 * 1296; i += 256) {
            int ic = i / 1296; int rem = i - ic * 1296;
            int yy = rem / 36, xx = rem - yy * 36;
            int gy = yy - 2, gx = xx - 2;
            float v = 0.f;
            if ((unsigned)gy < 32u && (unsigned)gx < 32u) v = pin[(icc + ic) * 1024 + gy * 32 + gx];
            s_in[ic * 1332 + yy * 37 + xx] = to_tf32(v);
        }
        for (int i = t; i < 512; i += 256) {    // 32 k x 16 oc
            int k = i >> 4, oc = i & 15;
            float v = 0.f;
            if (k < 30) { int ic = k / 5, s = k - ic * 5; v = pw[(oc * 48 + icc + ic) * 5 + s]; }
            s_w[k][oc] = to_tf32(v);
        }
        __syncthreads();
#pragma unroll
        for (int kt = 0; kt < 4; kt++) {
            unsigned a0 = s_w[kt * 8 + la][g];
            unsigned a1 = s_w[kt * 8 + la][g + 8];
            unsigned a2 = s_w[kt * 8 + la + 4][g];
            unsigned a3 = s_w[kt * 8 + la + 4][g + 8];
#pragma unroll
            for (int lr = 0; lr < 4; lr++) {
                int rowbase = (4 * wid + lr + 2) * 37 + 2 + g;
#pragma unroll
                for (int cg = 0; cg < 4; cg++) {
                    unsigned b0 = s_in[koff[kt][0] + rowbase + cg * 8];
                    unsigned b1 = s_in[koff[kt][1] + rowbase + cg * 8];
                    mma_tf32(acc[lr * 4 + cg], a0, a1, a2, a3, b0, b1);
                }
            }
        }
        __syncthreads();
    }
    // epilogue: exact fp32 stats of computed outputs + pooled raw 2x2 max.
    // C layout: thread holds oc=g (c0,c1) and oc=g+8 (c2,c3); pixel row 4w+lr,
    // cols 8*cg + 2*la, +1.
    float s_lo = 0.f, q_lo = 0.f, s_hi = 0.f, q_hi = 0.f;
#pragma unroll
    for (int nt = 0; nt < 16; nt++) {
        s_lo += acc[nt][0] + acc[nt][1];
        q_lo += acc[nt][0] * acc[nt][0] + acc[nt][1] * acc[nt][1];
        s_hi += acc[nt][2] + acc[nt][3];
        q_hi += acc[nt][2] * acc[nt][2] + acc[nt][3] * acc[nt][3];
    }
#pragma unroll
    for (int off = 1; off <= 2; off <<= 1) {
        s_lo += __shfl_xor_sync(0xffffffffu, s_lo, off);
        q_lo += __shfl_xor_sync(0xffffffffu, q_lo, off);
        s_hi += __shfl_xor_sync(0xffffffffu, s_hi, off);
        q_hi += __shfl_xor_sync(0xffffffffu, q_hi, off);
    }
    if (la == 0) {
        rs[g][wid] = s_lo;     rq[g][wid] = q_lo;
        rs[g + 8][wid] = s_hi; rq[g + 8][wid] = q_hi;
    }
    // pooled 2x2 max: horizontal pair in (c0,c1)/(c2,c3); vertical pair = lr 0/1 and 2/3
    size_t plane_lo = ((size_t)(b * 128 + r * 16 + g)) * 256;
    size_t plane_hi = plane_lo + (size_t)8 * 256;
#pragma unroll
    for (int lrp = 0; lrp < 2; lrp++) {
        int prow = 2 * wid + lrp;
#pragma unroll
        for (int cg = 0; cg < 4; cg++) {
            int nta = (2 * lrp) * 4 + cg, ntb = (2 * lrp + 1) * 4 + cg;
            float mlo = fmaxf(fmaxf(acc[nta][0], acc[nta][1]),
                              fmaxf(acc[ntb][0], acc[ntb][1]));
            float mhi = fmaxf(fmaxf(acc[nta][2], acc[nta][3]),
                              fmaxf(acc[ntb][2], acc[ntb][3]));
            g_q2[plane_lo + prow * 16 + cg * 4 + la] = mlo;
            g_q2[plane_hi + prow * 16 + cg * 4 + la] = mhi;
        }
    }
    __syncthreads();
    if (t < 16) {
        float S = 0.f, Q = 0.f;
#pragma unroll
        for (int wdx = 0; wdx < 8; wdx++) { S += rs[t][wdx]; Q += rq[t][wdx]; }
        int p = (b * 8 + r) * 16 + t;
        g_psum[p] = S; g_psq[p] = Q;
    }
}

// ======== conv3: 2 batches/block, scalar FFMA (R10) -> spatial max ========
__global__ __launch_bounds__(256, 4) void k_conv3()
{
    __shared__ float s_in[4][2][400];                 // 12800 B [ic][batch][20x20]
    __shared__ __align__(16) float s_w[4][10][8];     // 1280 B
    __shared__ float rmax[20][8];                     // 640 B
    int bb = blockIdx.x, r = blockIdx.y, cls = r & 3; // bb: 0..127 (batch pairs)
    int t = threadIdx.x;
    int oy[5], ox[5]; taps(cls, oy, ox);
    int boff[5];
#pragma unroll
    for (int s = 0; s < 5; s++) boff[s] = oy[s] * 20 + ox[s];
    int y = t >> 4, x = t & 15;
    int base = (y + 2) * 20 + x + 2;
    float acc[2][10];
#pragma unroll
    for (int b_ = 0; b_ < 2; b_++)
#pragma unroll
        for (int oc = 0; oc < 10; oc++) acc[b_][oc] = 0.f;
    const float* pw = g_sw3 + (size_t)r * 10 * 128 * 5;
    for (int icc = 0; icc < 128; icc += 4) {
        for (int i = t; i < 3200; i += 256) {
            int ic = i / 800; int rem = i - ic * 800;
            int b_ = rem / 400; int rem2 = rem - b_ * 400;
            int yy = rem2 / 20, xx = rem2 - yy * 20;
            int gy = yy - 2, gx = xx - 2;
            float v = 0.f;
            if ((unsigned)gy < 16u && (unsigned)gx < 16u)
                v = g_p2[(((size_t)(bb * 2 + b_) * 128) + icc + ic) * 256 + gy * 16 + gx];
            s_in[ic][b_][rem2] = v;
        }
        if (t < 200) {          // 4 ic x 10 oc x 5 s
            int ic = t / 50; int rem = t - ic * 50; int oc = rem / 5; int s = rem - oc * 5;
            s_w[ic][oc][s] = pw[(oc * 128 + icc + ic) * 5 + s];
        }
        __syncthreads();
#pragma unroll 1
        for (int ic = 0; ic < 4; ic++) {
            float in5[5][2];
#pragma unroll
            for (int s = 0; s < 5; s++) {
                in5[s][0] = s_in[ic][0][base + boff[s]];
                in5[s][1] = s_in[ic][1][base + boff[s]];
            }
#pragma unroll
            for (int oc = 0; oc < 10; oc++) {
                float4 w03 = *(const float4*)&s_w[ic][oc][0];
                float  w4  = s_w[ic][oc][4];
#pragma unroll
                for (int b_ = 0; b_ < 2; b_++) {
                    float a = acc[b_][oc];
                    a = fmaf(w03.x, in5[0][b_], a);
                    a = fmaf(w03.y, in5[1][b_], a);
                    a = fmaf(w03.z, in5[2][b_], a);
                    a = fmaf(w03.w, in5[3][b_], a);
                    a = fmaf(w4,   in5[4][b_], a);
                    acc[b_][oc] = a;
                }
            }
        }
        __syncthreads();
    }
    // in-block spatial max per (b_, oc)
    int lane = t & 31, wid = t >> 5;
#pragma unroll
    for (int b_ = 0; b_ < 2; b_++)
#pragma unroll
        for (int oc = 0; oc < 10; oc++) {
            float m = acc[b_][oc];
#pragma unroll
            for (int off = 16; off; off >>= 1)
                m = fmaxf(m, __shfl_down_sync(0xffffffffu, m, off));
            if (lane == 0) rmax[b_ * 10 + oc][wid] = m;
        }
    __syncthreads();
    if (t < 20) {
        float m = -3.4e38f;
#pragma unroll
        for (int wdx = 0; wdx < 8; wdx++) m = fmaxf(m, rmax[t][wdx]);
        int b_ = t / 10, oc = t - b_ * 10;
        g_m3[(size_t)(bb * 2 + b_) * 80 + r * 10 + oc] = m;
    }
}

// ---------------- rotateMax (groups of 8 consecutive channels) ----------------
__global__ void k_finalmax2(float* __restrict__ out)
{
    int i = blockIdx.x * blockDim.x + threadIdx.x;   // 2560 = 256 b x 10 groups
    if (i >= 2560) return;
    int b = i / 10, gp = i - b * 10;
    const float* p = g_m3 + b * 80 + gp * 8;
    float m = p[0];
#pragma unroll
    for (int k = 1; k < 8; k++) m = fmaxf(m, p[k]);
    out[i] = m;
}

// ---------------- launch ----------------
extern "C" void kernel_launch(void* const* d_in, const int* in_sizes, int n_in,
                              void* d_out, int out_size)
{
    const float* x  = (const float*)d_in[0];
    const float* w1 = (const float*)d_in[1];
    const float* g1 = (const float*)d_in[2];
    const float* b1 = (const float*)d_in[3];
    const float* w2 = (const float*)d_in[4];
    const float* g2 = (const float*)d_in[5];
    const float* b2 = (const float*)d_in[6];
    const float* w3 = (const float*)d_in[7];
    float* out = (float*)d_out;

    float *pp1, *pq2, *pp2;
    cudaGetSymbolAddress((void**)&pp1, g_p1);
    cudaGetSymbolAddress((void**)&pq2, g_q2);
    cudaGetSymbolAddress((void**)&pp2, g_p2);

    k_build<<<65, 256>>>(w1, w2, w3);
    k_conv1_statspool<<<dim3(256, 8), 256>>>(x);
    k_stats_final<<<6, 256>>>(g1, b1, 6, 1.f / 8388608.f);     // N = 256*8*64*64
    k_bnrelu<<<12288, 256>>>(pp1, pp1, 48, 8);                 // p1 in place (256 f4/plane)
    k_conv2<<<dim3(256, 8), 256>>>();
    k_stats_final<<<16, 256>>>(g2, b2, 16, 1.f / 2097152.f);   // N = 256*8*32*32
    k_bnrelu<<<8192, 256>>>(pq2, pp2, 128, 6);                 // q2 -> p2 (64 f4/plane)
    k_conv3<<<dim3(128, 8), 256>>>();
    k_finalmax2<<<10, 256>>>(out);
}